// round 7
// baseline (speedup 1.0000x reference)
#include <cuda_runtime.h>
#include <cuda_bf16.h>
#include <cstdint>

// ---------------------------------------------------------------------------
// Problem constants
// ---------------------------------------------------------------------------
#define T_TOK 8192
#define NJ    24
#define DIM   256
#define NH    8
#define FD    32
#define ND    6144                 // NJ*DIM

// Scratch (bf16): Q/K/V in [t][h][n][f] layout; pre-transposed weights K-major.
__device__ __nv_bfloat16 g_Q[(size_t)T_TOK * NH * NJ * FD];
__device__ __nv_bfloat16 g_K[(size_t)T_TOK * NH * NJ * FD];
__device__ __nv_bfloat16 g_V[(size_t)T_TOK * NH * NJ * FD];
__device__ __nv_bfloat16 g_WqT[(size_t)NJ * 256 * 256];  // [n][c][d]
__device__ __nv_bfloat16 g_WkT[256 * 256];               // [c][d]
__device__ __nv_bfloat16 g_WvT[256 * 256];

__device__ __forceinline__ uint32_t smem_u32(const void* p) {
    uint32_t a;
    asm("{ .reg .u64 t; cvta.to.shared.u64 t, %1; cvt.u32.u64 %0, t; }" : "=r"(a) : "l"(p));
    return a;
}

__device__ __forceinline__ void ldmatrix_x4(uint32_t* r, uint32_t addr) {
    asm volatile("ldmatrix.sync.aligned.m8n8.x4.shared.b16 {%0,%1,%2,%3}, [%4];"
                 : "=r"(r[0]), "=r"(r[1]), "=r"(r[2]), "=r"(r[3]) : "r"(addr));
}

__device__ __forceinline__ void mma_bf16(float* c, const uint32_t* a, const uint32_t* b) {
    asm volatile("mma.sync.aligned.m16n8k16.row.col.f32.bf16.bf16.f32 "
                 "{%0,%1,%2,%3}, {%4,%5,%6,%7}, {%8,%9}, {%0,%1,%2,%3};"
                 : "+f"(c[0]), "+f"(c[1]), "+f"(c[2]), "+f"(c[3])
                 : "r"(a[0]), "r"(a[1]), "r"(a[2]), "r"(a[3]), "r"(b[0]), "r"(b[1]));
}

// ---------------------------------------------------------------------------
// Prep: transpose + convert weights to K-major bf16.
// ---------------------------------------------------------------------------
__global__ void prep_w(const float* __restrict__ Wq, const float* __restrict__ Wk,
                       const float* __restrict__ Wv) {
    const int NQ = NJ * 65536;
    int i = blockIdx.x * 256 + threadIdx.x;
    if (i < NQ) {
        int n = i >> 16, rem = i & 65535, c = rem >> 8, d = rem & 255;
        int h = c >> 5, f = c & 31;
        g_WqT[i] = __float2bfloat16(Wq[(((size_t)(h * NJ + n) * 256) + d) * 32 + f]);
    } else if (i < NQ + 65536) {
        int j = i - NQ, c = j >> 8, d = j & 255, h = c >> 5, f = c & 31;
        g_WkT[j] = __float2bfloat16(Wk[((size_t)(h * 256 + d)) * 32 + f]);
    } else if (i < NQ + 131072) {
        int j = i - NQ - 65536, c = j >> 8, d = j & 255, h = c >> 5, f = c & 31;
        g_WvT[j] = __float2bfloat16(Wv[((size_t)(h * 256 + d)) * 32 + f]);
    }
}

// ---------------------------------------------------------------------------
// Fused QKV GEMM. CTA = (128 tokens, joint n). A tile resident in smem;
// 6 sections (Q/K/V x 2 col halves) stream a double-buffered B tile.
// Epilogue staged through the Bs region (two 64-row phases) for coalesced
// 64B-unit STG.128 stores.
// ---------------------------------------------------------------------------
#define ASTR_A 264   // 256 + 8 pad (bf16)
#define ASTR_B 40    // 32 + 8 pad
#define SSTR   136   // stage stride (bf16 elems), 272B, 16B-aligned

__global__ __launch_bounds__(256, 2)
void fused_qkv(const float* __restrict__ x,
               const float* __restrict__ bq, const float* __restrict__ bk,
               const float* __restrict__ bv) {
    extern __shared__ char smem[];
    __nv_bfloat16* As = (__nv_bfloat16*)smem;                     // 128*264*2 = 67584
    __nv_bfloat16* Bs = (__nv_bfloat16*)(smem + 67584);           // 2 x 10240 (also stage)
    float* sbias      = (float*)(smem + 67584 + 20480);           // 768 floats

    const int tid  = threadIdx.x;
    const int lane = tid & 31;
    const int wid  = tid >> 5;
    const int wm   = (wid & 3) * 32;    // warp m offset
    const int wn   = (wid >> 2) * 64;   // warp n offset (within 128-col section)

    const int n    = blockIdx.y;        // joint
    const size_t row0 = (size_t)blockIdx.x * 128;

    {
        const int c = tid, h = c >> 5, f = c & 31;
        sbias[c]       = bq[(h * NJ + n) * FD + f];
        sbias[256 + c] = bk[c];
        sbias[512 + c] = bv[c];
    }

    // ---- load A tile: x[row0..+128, n*256..+256] fp32 -> bf16 smem ----
    {
        const float* ab = x + row0 * (size_t)ND + (size_t)n * DIM;
        #pragma unroll
        for (int p = 0; p < 32; p++) {
            const int flat = tid + p * 256;
            const int row  = flat >> 6;
            const int col  = (flat & 63) * 4;
            const float4 v = *(const float4*)(ab + (size_t)row * ND + col);
            __nv_bfloat162 p0 = __float22bfloat162_rn(make_float2(v.x, v.y));
            __nv_bfloat162 p1 = __float22bfloat162_rn(make_float2(v.z, v.w));
            uint2 w; w.x = *(uint32_t*)&p0; w.y = *(uint32_t*)&p1;
            *(uint2*)&As[row * ASTR_A + col] = w;
        }
    }

    const __nv_bfloat16* WTs[3] = { g_WqT + (size_t)n * 65536, g_WkT, g_WvT };
    __nv_bfloat16* dsts[3] = { g_Q, g_K, g_V };

    const uint32_t as_base = smem_u32(As);
    const uint32_t bs_base = smem_u32(Bs);
    const int lmat = lane >> 3, lr = lane & 7;

    const int bRow = tid >> 1, bSeg = (tid & 1) * 16;

    float acc[2][8][4] = {};
    uint4 bReg[2];
    {
        const __nv_bfloat16* bp = WTs[0] + (size_t)bRow * 256 + bSeg;
        bReg[0] = ((const uint4*)bp)[0];
        bReg[1] = ((const uint4*)bp)[1];
    }

    #pragma unroll 1
    for (int sc = 0; sc < 48; sc++) {
        const int sec   = sc >> 3;
        const int chunk = sc & 7;
        const int which = sec >> 1;
        const int c0    = (sec & 1) * 128;
        const int buf   = (sc & 1) * 128 * ASTR_B;

        *(uint4*)&Bs[buf + bRow * ASTR_B + bSeg + 0] = bReg[0];
        *(uint4*)&Bs[buf + bRow * ASTR_B + bSeg + 8] = bReg[1];
        __syncthreads();

        if (sc < 47) {
            const int nsc = sc + 1;
            const int nsec = nsc >> 3, nch = nsc & 7;
            const __nv_bfloat16* bp = WTs[nsec >> 1]
                + (size_t)((nsec & 1) * 128 + bRow) * 256 + nch * 32 + bSeg;
            bReg[0] = ((const uint4*)bp)[0];
            bReg[1] = ((const uint4*)bp)[1];
        }

        #pragma unroll
        for (int kh = 0; kh < 2; kh++) {
            uint32_t af[2][4], bf[4][4];
            #pragma unroll
            for (int i = 0; i < 2; i++) {
                const int row = wm + i * 16 + (lmat & 1) * 8 + lr;
                const int col = chunk * 32 + kh * 16 + (lmat >> 1) * 8;
                ldmatrix_x4(af[i], as_base + (row * ASTR_A + col) * 2);
            }
            #pragma unroll
            for (int j = 0; j < 4; j++) {
                const int row = wn + j * 16 + (lmat >> 1) * 8 + lr;
                const int col = kh * 16 + (lmat & 1) * 8;
                ldmatrix_x4(bf[j], bs_base + (buf + row * ASTR_B + col) * 2);
            }
            #pragma unroll
            for (int i = 0; i < 2; i++)
                #pragma unroll
                for (int jj = 0; jj < 8; jj++)
                    mma_bf16(acc[i][jj], af[i], &bf[jj >> 1][(jj & 1) * 2]);
        }

        if (chunk == 7) {
            // Staged epilogue: two phases of 64 rows each through Bs region.
            __nv_bfloat16* dst = dsts[which];
            #pragma unroll 1
            for (int iph = 0; iph < 2; iph++) {
                __syncthreads();   // all Bs reads (compute / prior phase STG) done
                // stage: acc(+bias) -> bf16 [lrs][cl], stride SSTR
                #pragma unroll
                for (int jj = 0; jj < 8; jj++) {
                    const int cl = wn + jj * 8 + (lane & 3) * 2;
                    const int c  = c0 + cl;
                    const float b0 = sbias[which * 256 + c];
                    const float b1 = sbias[which * 256 + c + 1];
                    #pragma unroll
                    for (int half = 0; half < 2; half++) {
                        const int lrs = (wm >> 1) + (lane >> 2) + half * 8;
                        __nv_bfloat162 pk = __float22bfloat162_rn(
                            make_float2(acc[iph][jj][half * 2] + b0,
                                        acc[iph][jj][half * 2 + 1] + b1));
                        *(__nv_bfloat162*)&Bs[lrs * SSTR + cl] = pk;
                        acc[iph][jj][half * 2] = 0.f;
                        acc[iph][jj][half * 2 + 1] = 0.f;
                    }
                }
                __syncthreads();
                // coalesced write: 64B (t,h) units via STG.128
                #pragma unroll
                for (int p = 0; p < 4; p++) {
                    const int task = tid + p * 256;
                    const int seg  = task & 3;
                    const int u    = task >> 2;       // 0..255
                    const int hl   = u & 3;
                    const int srow = u >> 2;          // 0..63
                    const int tl   = ((srow >> 4) * 32) + iph * 16 + (srow & 15);
                    const size_t t = row0 + tl;
                    const int h    = (sec & 1) * 4 + hl;
                    const uint4 val = *(const uint4*)&Bs[srow * SSTR + hl * 32 + seg * 8];
                    *(uint4*)(dst + (((t * NH + h) * NJ + n) * FD) + seg * 8) = val;
                }
            }
            __syncthreads();   // stage reads done before next iter's B store
        }
    }
}

// ---------------------------------------------------------------------------
// Attention + residual + LayerNorm. 192 threads = (h, n) pairs per token.
// K/V staged as raw bf16; after PV, their 24KB region is reused as the fp32
// ob buffer (smem 49KB -> 24.7KB => 3 CTAs/SM).
// ---------------------------------------------------------------------------
__global__ __launch_bounds__(192)
void attn_ln(const float* __restrict__ x, const float* __restrict__ gamma,
             const float* __restrict__ beta, float* __restrict__ outg) {
    extern __shared__ float sm[];
    __nv_bfloat16* ksh = (__nv_bfloat16*)sm;     // [0, 12KB)
    __nv_bfloat16* vsh = ksh + ND;               // [12KB, 24KB)
    float* ob  = sm;                             // aliases ksh+vsh after PV
    float* red = sm + ND;                        // at 24KB

    const int t = blockIdx.x;
    const int tid = threadIdx.x;
    const int h = tid / 24, n = tid - h * 24;
    const int w = tid >> 5, lane = tid & 31;

    // stage K/V as raw bf16 (uint4 copies)
    const uint4* kb = (const uint4*)(g_K + (size_t)t * ND);
    const uint4* vb = (const uint4*)(g_V + (size_t)t * ND);
    uint4* k4 = (uint4*)ksh;
    uint4* v4 = (uint4*)vsh;
    #pragma unroll
    for (int p = 0; p < 4; p++) {
        const int i = tid + p * 192;
        k4[i] = kb[i];
        v4[i] = vb[i];
    }
    // own q row -> fp32 regs
    float q[FD];
    {
        const uint4* qp = (const uint4*)(g_Q + (size_t)t * ND + (h * NJ + n) * FD);
        #pragma unroll
        for (int j = 0; j < 4; j++) {
            const uint4 wv = qp[j];
            *(float2*)(q + j * 8 + 0) = __bfloat1622float2(*(__nv_bfloat162*)&wv.x);
            *(float2*)(q + j * 8 + 2) = __bfloat1622float2(*(__nv_bfloat162*)&wv.y);
            *(float2*)(q + j * 8 + 4) = __bfloat1622float2(*(__nv_bfloat162*)&wv.z);
            *(float2*)(q + j * 8 + 6) = __bfloat1622float2(*(__nv_bfloat162*)&wv.w);
        }
    }
    __syncthreads();

    // scores
    float s[NJ];
    float mx = -1e30f;
    #pragma unroll
    for (int m = 0; m < NJ; m++) {
        const uint4* kr = (const uint4*)(ksh + (h * NJ + m) * FD);
        float a = 0.f;
        #pragma unroll
        for (int j = 0; j < 4; j++) {
            const uint4 wv = kr[j];
            const float2 c0 = __bfloat1622float2(*(__nv_bfloat162*)&wv.x);
            const float2 c1 = __bfloat1622float2(*(__nv_bfloat162*)&wv.y);
            const float2 c2 = __bfloat1622float2(*(__nv_bfloat162*)&wv.z);
            const float2 c3 = __bfloat1622float2(*(__nv_bfloat162*)&wv.w);
            a += q[j*8+0]*c0.x + q[j*8+1]*c0.y + q[j*8+2]*c1.x + q[j*8+3]*c1.y
               + q[j*8+4]*c2.x + q[j*8+5]*c2.y + q[j*8+6]*c3.x + q[j*8+7]*c3.y;
        }
        s[m] = a * 0.17677669529663687f;
        mx = fmaxf(mx, s[m]);
    }
    float sum = 0.f;
    #pragma unroll
    for (int m = 0; m < NJ; m++) { s[m] = __expf(s[m] - mx); sum += s[m]; }
    const float inv = 1.0f / sum;
    #pragma unroll
    for (int m = 0; m < NJ; m++) s[m] *= inv;

    // PV -> o (registers only)
    float o[FD] = {};
    #pragma unroll
    for (int m = 0; m < NJ; m++) {
        const uint4* vr = (const uint4*)(vsh + (h * NJ + m) * FD);
        const float sv = s[m];
        #pragma unroll
        for (int j = 0; j < 4; j++) {
            const uint4 wv = vr[j];
            const float2 c0 = __bfloat1622float2(*(__nv_bfloat162*)&wv.x);
            const float2 c1 = __bfloat1622float2(*(__nv_bfloat162*)&wv.y);
            const float2 c2 = __bfloat1622float2(*(__nv_bfloat162*)&wv.z);
            const float2 c3 = __bfloat1622float2(*(__nv_bfloat162*)&wv.w);
            o[j*8+0] += sv*c0.x; o[j*8+1] += sv*c0.y;
            o[j*8+2] += sv*c1.x; o[j*8+3] += sv*c1.y;
            o[j*8+4] += sv*c2.x; o[j*8+5] += sv*c2.y;
            o[j*8+6] += sv*c3.x; o[j*8+7] += sv*c3.y;
        }
    }
    __syncthreads();   // all ksh/vsh reads done -> safe to alias as ob

    {
        float4* op = (float4*)(ob + n * (NH * FD) + h * FD);
        #pragma unroll
        for (int j = 0; j < 8; j++)
            op[j] = make_float4(o[4*j], o[4*j+1], o[4*j+2], o[4*j+3]);
    }
    __syncthreads();

    // residual + LN over 6144 (coalesced)
    float lsum = 0.f, lsq = 0.f;
    const float4* xr = (const float4*)(x + (size_t)t * ND);
    float4* ob4 = (float4*)ob;
    #pragma unroll
    for (int p = 0; p < 8; p++) {
        const int i = tid + p * 192;
        float4 y = xr[i];
        const float4 a = ob4[i];
        y.x += a.x; y.y += a.y; y.z += a.z; y.w += a.w;
        ob4[i] = y;
        lsum += y.x + y.y + y.z + y.w;
        lsq  += y.x*y.x + y.y*y.y + y.z*y.z + y.w*y.w;
    }
    #pragma unroll
    for (int off = 16; off > 0; off >>= 1) {
        lsum += __shfl_xor_sync(0xFFFFFFFFu, lsum, off);
        lsq  += __shfl_xor_sync(0xFFFFFFFFu, lsq,  off);
    }
    if (lane == 0) { red[w] = lsum; red[8 + w] = lsq; }
    __syncthreads();
    if (tid == 0) {
        float a = 0.f, b = 0.f;
        #pragma unroll
        for (int i = 0; i < 6; i++) { a += red[i]; b += red[8 + i]; }
        const float mu = a / (float)ND;
        const float var = b / (float)ND - mu * mu;
        red[16] = mu;
        red[17] = rsqrtf(var + 1e-5f);
    }
    __syncthreads();
    const float mu = red[16], rstd = red[17];
    const float4* g4 = (const float4*)gamma;
    const float4* b4 = (const float4*)beta;
    float4* orow = (float4*)(outg + (size_t)t * ND);
    #pragma unroll
    for (int p = 0; p < 8; p++) {
        const int i = tid + p * 192;
        const float4 y = ob4[i], gg = g4[i], bb = b4[i];
        orow[i] = make_float4((y.x - mu) * rstd * gg.x + bb.x,
                              (y.y - mu) * rstd * gg.y + bb.y,
                              (y.z - mu) * rstd * gg.z + bb.z,
                              (y.w - mu) * rstd * gg.w + bb.w);
    }
}

// ---------------------------------------------------------------------------
extern "C" void kernel_launch(void* const* d_in, const int* in_sizes, int n_in,
                              void* d_out, int out_size) {
    const float* x     = (const float*)d_in[0];
    const float* Wq    = (const float*)d_in[1];
    const float* bq    = (const float*)d_in[2];
    const float* Wk    = (const float*)d_in[3];
    const float* bk    = (const float*)d_in[4];
    const float* Wv    = (const float*)d_in[5];
    const float* bv    = (const float*)d_in[6];
    const float* gamma = (const float*)d_in[7];
    const float* beta  = (const float*)d_in[8];
    float* out = (float*)d_out;

    prep_w<<<6656, 256>>>(Wq, Wk, Wv);

    const int SMEM_G = 67584 + 20480 + 768 * 4;   // 91136
    cudaFuncSetAttribute(fused_qkv, cudaFuncAttributeMaxDynamicSharedMemorySize, SMEM_G);
    fused_qkv<<<dim3(T_TOK / 128, NJ), 256, SMEM_G>>>(x, bq, bk, bv);

    const int SMEM_ATTN = ND * 4 + 128;   // 24704
    cudaFuncSetAttribute(attn_ln, cudaFuncAttributeMaxDynamicSharedMemorySize, SMEM_ATTN);
    attn_ln<<<T_TOK, 192, SMEM_ATTN>>>(x, gamma, beta, out);
}

// round 8
// speedup vs baseline: 1.9822x; 1.9822x over previous
#include <cuda_runtime.h>
#include <cuda_bf16.h>
#include <cstdint>

// ---------------------------------------------------------------------------
// Problem constants
// ---------------------------------------------------------------------------
#define T_TOK 8192
#define NJ    24
#define DIM   256
#define NH    8
#define FD    32
#define ND    6144                 // NJ*DIM

// Scratch (bf16): Q/K/V in [t][h][n][f] layout; pre-transposed weights K-major.
__device__ __nv_bfloat16 g_Q[(size_t)T_TOK * NH * NJ * FD];
__device__ __nv_bfloat16 g_K[(size_t)T_TOK * NH * NJ * FD];
__device__ __nv_bfloat16 g_V[(size_t)T_TOK * NH * NJ * FD];
__device__ __nv_bfloat16 g_WqT[(size_t)NJ * 256 * 256];  // [n][c][d]
__device__ __nv_bfloat16 g_WkT[256 * 256];               // [c][d]
__device__ __nv_bfloat16 g_WvT[256 * 256];

__device__ __forceinline__ uint32_t smem_u32(const void* p) {
    uint32_t a;
    asm("{ .reg .u64 t; cvta.to.shared.u64 t, %1; cvt.u32.u64 %0, t; }" : "=r"(a) : "l"(p));
    return a;
}

__device__ __forceinline__ void ldmatrix_x4(uint32_t* r, uint32_t addr) {
    asm volatile("ldmatrix.sync.aligned.m8n8.x4.shared.b16 {%0,%1,%2,%3}, [%4];"
                 : "=r"(r[0]), "=r"(r[1]), "=r"(r[2]), "=r"(r[3]) : "r"(addr));
}

__device__ __forceinline__ void mma_bf16(float* c, const uint32_t* a, const uint32_t* b) {
    asm volatile("mma.sync.aligned.m16n8k16.row.col.f32.bf16.bf16.f32 "
                 "{%0,%1,%2,%3}, {%4,%5,%6,%7}, {%8,%9}, {%0,%1,%2,%3};"
                 : "+f"(c[0]), "+f"(c[1]), "+f"(c[2]), "+f"(c[3])
                 : "r"(a[0]), "r"(a[1]), "r"(a[2]), "r"(a[3]), "r"(b[0]), "r"(b[1]));
}

// ---------------------------------------------------------------------------
// Prep: transpose + convert weights to K-major bf16.
// ---------------------------------------------------------------------------
__global__ void prep_w(const float* __restrict__ Wq, const float* __restrict__ Wk,
                       const float* __restrict__ Wv) {
    const int NQ = NJ * 65536;
    int i = blockIdx.x * 256 + threadIdx.x;
    if (i < NQ) {
        int n = i >> 16, rem = i & 65535, c = rem >> 8, d = rem & 255;
        int h = c >> 5, f = c & 31;
        g_WqT[i] = __float2bfloat16(Wq[(((size_t)(h * NJ + n) * 256) + d) * 32 + f]);
    } else if (i < NQ + 65536) {
        int j = i - NQ, c = j >> 8, d = j & 255, h = c >> 5, f = c & 31;
        g_WkT[j] = __float2bfloat16(Wk[((size_t)(h * 256 + d)) * 32 + f]);
    } else if (i < NQ + 131072) {
        int j = i - NQ - 65536, c = j >> 8, d = j & 255, h = c >> 5, f = c & 31;
        g_WvT[j] = __float2bfloat16(Wv[((size_t)(h * 256 + d)) * 32 + f]);
    }
}

// ---------------------------------------------------------------------------
// Fused QKV GEMM (round-6 structure: direct-scatter epilogue, fully unrolled
// constant acc indexing; double-buffered B tile, one sync per chunk).
// ---------------------------------------------------------------------------
#define ASTR_A 264   // 256 + 8 pad (bf16)
#define ASTR_B 40    // 32 + 8 pad

__global__ __launch_bounds__(256, 2)
void fused_qkv(const float* __restrict__ x,
               const float* __restrict__ bq, const float* __restrict__ bk,
               const float* __restrict__ bv) {
    extern __shared__ char smem[];
    __nv_bfloat16* As = (__nv_bfloat16*)smem;                     // 128*264*2 = 67584
    __nv_bfloat16* Bs = (__nv_bfloat16*)(smem + 67584);           // 2 x 10240
    float* sbias      = (float*)(smem + 67584 + 20480);           // 768 floats

    const int tid  = threadIdx.x;
    const int lane = tid & 31;
    const int wid  = tid >> 5;
    const int wm   = (wid & 3) * 32;    // warp m offset
    const int wn   = (wid >> 2) * 64;   // warp n offset (within 128-col section)

    const int n    = blockIdx.y;        // joint
    const size_t row0 = (size_t)blockIdx.x * 128;

    {
        const int c = tid, h = c >> 5, f = c & 31;
        sbias[c]       = bq[(h * NJ + n) * FD + f];
        sbias[256 + c] = bk[c];
        sbias[512 + c] = bv[c];
    }

    // ---- load A tile: x[row0..+128, n*256..+256] fp32 -> bf16 smem ----
    {
        const float* ab = x + row0 * (size_t)ND + (size_t)n * DIM;
        #pragma unroll
        for (int p = 0; p < 32; p++) {
            const int flat = tid + p * 256;
            const int row  = flat >> 6;
            const int col  = (flat & 63) * 4;
            const float4 v = *(const float4*)(ab + (size_t)row * ND + col);
            __nv_bfloat162 p0 = __float22bfloat162_rn(make_float2(v.x, v.y));
            __nv_bfloat162 p1 = __float22bfloat162_rn(make_float2(v.z, v.w));
            uint2 w; w.x = *(uint32_t*)&p0; w.y = *(uint32_t*)&p1;
            *(uint2*)&As[row * ASTR_A + col] = w;
        }
    }

    const __nv_bfloat16* WTs[3] = { g_WqT + (size_t)n * 65536, g_WkT, g_WvT };
    __nv_bfloat16* dsts[3] = { g_Q, g_K, g_V };

    const uint32_t as_base = smem_u32(As);
    const uint32_t bs_base = smem_u32(Bs);
    const int lmat = lane >> 3, lr = lane & 7;

    const int bRow = tid >> 1, bSeg = (tid & 1) * 16;

    float acc[2][8][4] = {};
    uint4 bReg[2];
    {
        const __nv_bfloat16* bp = WTs[0] + (size_t)bRow * 256 + bSeg;
        bReg[0] = ((const uint4*)bp)[0];
        bReg[1] = ((const uint4*)bp)[1];
    }

    #pragma unroll 1
    for (int sc = 0; sc < 48; sc++) {
        const int sec   = sc >> 3;
        const int chunk = sc & 7;
        const int which = sec >> 1;
        const int c0    = (sec & 1) * 128;
        const int buf   = (sc & 1) * 128 * ASTR_B;

        // store staged B regs into buffer; reads of this buffer (iteration
        // sc-2) finished before every warp arrived at sync(sc-1).
        *(uint4*)&Bs[buf + bRow * ASTR_B + bSeg + 0] = bReg[0];
        *(uint4*)&Bs[buf + bRow * ASTR_B + bSeg + 8] = bReg[1];
        __syncthreads();

        if (sc < 47) {
            const int nsc = sc + 1;
            const int nsec = nsc >> 3, nch = nsc & 7;
            const __nv_bfloat16* bp = WTs[nsec >> 1]
                + (size_t)((nsec & 1) * 128 + bRow) * 256 + nch * 32 + bSeg;
            bReg[0] = ((const uint4*)bp)[0];
            bReg[1] = ((const uint4*)bp)[1];
        }

        #pragma unroll
        for (int kh = 0; kh < 2; kh++) {
            uint32_t af[2][4], bf[4][4];
            #pragma unroll
            for (int i = 0; i < 2; i++) {
                const int row = wm + i * 16 + (lmat & 1) * 8 + lr;
                const int col = chunk * 32 + kh * 16 + (lmat >> 1) * 8;
                ldmatrix_x4(af[i], as_base + (row * ASTR_A + col) * 2);
            }
            #pragma unroll
            for (int j = 0; j < 4; j++) {
                const int row = wn + j * 16 + (lmat >> 1) * 8 + lr;
                const int col = kh * 16 + (lmat & 1) * 8;
                ldmatrix_x4(bf[j], bs_base + (buf + row * ASTR_B + col) * 2);
            }
            #pragma unroll
            for (int i = 0; i < 2; i++)
                #pragma unroll
                for (int jj = 0; jj < 8; jj++)
                    mma_bf16(acc[i][jj], af[i], &bf[jj >> 1][(jj & 1) * 2]);
        }

        if (chunk == 7) {
            __nv_bfloat16* dst = dsts[which];
            #pragma unroll
            for (int i = 0; i < 2; i++) {
                #pragma unroll
                for (int jj = 0; jj < 8; jj++) {
                    const int cl = wn + jj * 8 + (lane & 3) * 2;
                    const int c  = c0 + cl;
                    const int h = c >> 5, f = c & 31;
                    const float b0 = sbias[which * 256 + c];
                    const float b1 = sbias[which * 256 + c + 1];
                    #pragma unroll
                    for (int half = 0; half < 2; half++) {
                        const size_t t = row0 + wm + i * 16 + (lane >> 2) + half * 8;
                        __nv_bfloat162 pk = __float22bfloat162_rn(
                            make_float2(acc[i][jj][half * 2] + b0,
                                        acc[i][jj][half * 2 + 1] + b1));
                        *(__nv_bfloat162*)(dst + (((t * NH + h) * NJ + n) * FD) + f) = pk;
                        acc[i][jj][half * 2] = 0.f;
                        acc[i][jj][half * 2 + 1] = 0.f;
                    }
                }
            }
        }
    }
}

// ---------------------------------------------------------------------------
// Attention + residual + LayerNorm. 192 threads = (h, n) pairs per token.
// K/V staged as raw bf16; after PV, their 24KB region is reused as the fp32
// ob buffer (smem 24.7KB total => higher occupancy than 49KB version).
// ---------------------------------------------------------------------------
__global__ __launch_bounds__(192)
void attn_ln(const float* __restrict__ x, const float* __restrict__ gamma,
             const float* __restrict__ beta, float* __restrict__ outg) {
    extern __shared__ float sm[];
    __nv_bfloat16* ksh = (__nv_bfloat16*)sm;     // [0, 12KB)
    __nv_bfloat16* vsh = ksh + ND;               // [12KB, 24KB)
    float* ob  = sm;                             // aliases ksh+vsh after PV
    float* red = sm + ND;                        // at 24KB

    const int t = blockIdx.x;
    const int tid = threadIdx.x;
    const int h = tid / 24, n = tid - h * 24;
    const int w = tid >> 5, lane = tid & 31;

    // stage K/V as raw bf16 (uint4 copies)
    const uint4* kb = (const uint4*)(g_K + (size_t)t * ND);
    const uint4* vb = (const uint4*)(g_V + (size_t)t * ND);
    uint4* k4 = (uint4*)ksh;
    uint4* v4 = (uint4*)vsh;
    #pragma unroll
    for (int p = 0; p < 4; p++) {
        const int i = tid + p * 192;
        k4[i] = kb[i];
        v4[i] = vb[i];
    }
    // own q row -> fp32 regs
    float q[FD];
    {
        const uint4* qp = (const uint4*)(g_Q + (size_t)t * ND + (h * NJ + n) * FD);
        #pragma unroll
        for (int j = 0; j < 4; j++) {
            const uint4 wv = qp[j];
            *(float2*)(q + j * 8 + 0) = __bfloat1622float2(*(__nv_bfloat162*)&wv.x);
            *(float2*)(q + j * 8 + 2) = __bfloat1622float2(*(__nv_bfloat162*)&wv.y);
            *(float2*)(q + j * 8 + 4) = __bfloat1622float2(*(__nv_bfloat162*)&wv.z);
            *(float2*)(q + j * 8 + 6) = __bfloat1622float2(*(__nv_bfloat162*)&wv.w);
        }
    }
    __syncthreads();

    // scores
    float s[NJ];
    float mx = -1e30f;
    #pragma unroll
    for (int m = 0; m < NJ; m++) {
        const uint4* kr = (const uint4*)(ksh + (h * NJ + m) * FD);
        float a = 0.f;
        #pragma unroll
        for (int j = 0; j < 4; j++) {
            const uint4 wv = kr[j];
            const float2 c0 = __bfloat1622float2(*(__nv_bfloat162*)&wv.x);
            const float2 c1 = __bfloat1622float2(*(__nv_bfloat162*)&wv.y);
            const float2 c2 = __bfloat1622float2(*(__nv_bfloat162*)&wv.z);
            const float2 c3 = __bfloat1622float2(*(__nv_bfloat162*)&wv.w);
            a += q[j*8+0]*c0.x + q[j*8+1]*c0.y + q[j*8+2]*c1.x + q[j*8+3]*c1.y
               + q[j*8+4]*c2.x + q[j*8+5]*c2.y + q[j*8+6]*c3.x + q[j*8+7]*c3.y;
        }
        s[m] = a * 0.17677669529663687f;
        mx = fmaxf(mx, s[m]);
    }
    float sum = 0.f;
    #pragma unroll
    for (int m = 0; m < NJ; m++) { s[m] = __expf(s[m] - mx); sum += s[m]; }
    const float inv = 1.0f / sum;
    #pragma unroll
    for (int m = 0; m < NJ; m++) s[m] *= inv;

    // PV -> o (registers only)
    float o[FD] = {};
    #pragma unroll
    for (int m = 0; m < NJ; m++) {
        const uint4* vr = (const uint4*)(vsh + (h * NJ + m) * FD);
        const float sv = s[m];
        #pragma unroll
        for (int j = 0; j < 4; j++) {
            const uint4 wv = vr[j];
            const float2 c0 = __bfloat1622float2(*(__nv_bfloat162*)&wv.x);
            const float2 c1 = __bfloat1622float2(*(__nv_bfloat162*)&wv.y);
            const float2 c2 = __bfloat1622float2(*(__nv_bfloat162*)&wv.z);
            const float2 c3 = __bfloat1622float2(*(__nv_bfloat162*)&wv.w);
            o[j*8+0] += sv*c0.x; o[j*8+1] += sv*c0.y;
            o[j*8+2] += sv*c1.x; o[j*8+3] += sv*c1.y;
            o[j*8+4] += sv*c2.x; o[j*8+5] += sv*c2.y;
            o[j*8+6] += sv*c3.x; o[j*8+7] += sv*c3.y;
        }
    }
    __syncthreads();   // all ksh/vsh reads done -> safe to alias as ob

    {
        float4* op = (float4*)(ob + n * (NH * FD) + h * FD);
        #pragma unroll
        for (int j = 0; j < 8; j++)
            op[j] = make_float4(o[4*j], o[4*j+1], o[4*j+2], o[4*j+3]);
    }
    __syncthreads();

    // residual + LN over 6144 (coalesced)
    float lsum = 0.f, lsq = 0.f;
    const float4* xr = (const float4*)(x + (size_t)t * ND);
    float4* ob4 = (float4*)ob;
    #pragma unroll
    for (int p = 0; p < 8; p++) {
        const int i = tid + p * 192;
        float4 y = xr[i];
        const float4 a = ob4[i];
        y.x += a.x; y.y += a.y; y.z += a.z; y.w += a.w;
        ob4[i] = y;
        lsum += y.x + y.y + y.z + y.w;
        lsq  += y.x*y.x + y.y*y.y + y.z*y.z + y.w*y.w;
    }
    #pragma unroll
    for (int off = 16; off > 0; off >>= 1) {
        lsum += __shfl_xor_sync(0xFFFFFFFFu, lsum, off);
        lsq  += __shfl_xor_sync(0xFFFFFFFFu, lsq,  off);
    }
    if (lane == 0) { red[w] = lsum; red[8 + w] = lsq; }
    __syncthreads();
    if (tid == 0) {
        float a = 0.f, b = 0.f;
        #pragma unroll
        for (int i = 0; i < 6; i++) { a += red[i]; b += red[8 + i]; }
        const float mu = a / (float)ND;
        const float var = b / (float)ND - mu * mu;
        red[16] = mu;
        red[17] = rsqrtf(var + 1e-5f);
    }
    __syncthreads();
    const float mu = red[16], rstd = red[17];
    const float4* g4 = (const float4*)gamma;
    const float4* b4 = (const float4*)beta;
    float4* orow = (float4*)(outg + (size_t)t * ND);
    #pragma unroll
    for (int p = 0; p < 8; p++) {
        const int i = tid + p * 192;
        const float4 y = ob4[i], gg = g4[i], bb = b4[i];
        orow[i] = make_float4((y.x - mu) * rstd * gg.x + bb.x,
                              (y.y - mu) * rstd * gg.y + bb.y,
                              (y.z - mu) * rstd * gg.z + bb.z,
                              (y.w - mu) * rstd * gg.w + bb.w);
    }
}

// ---------------------------------------------------------------------------
extern "C" void kernel_launch(void* const* d_in, const int* in_sizes, int n_in,
                              void* d_out, int out_size) {
    const float* x     = (const float*)d_in[0];
    const float* Wq    = (const float*)d_in[1];
    const float* bq    = (const float*)d_in[2];
    const float* Wk    = (const float*)d_in[3];
    const float* bk    = (const float*)d_in[4];
    const float* Wv    = (const float*)d_in[5];
    const float* bv    = (const float*)d_in[6];
    const float* gamma = (const float*)d_in[7];
    const float* beta  = (const float*)d_in[8];
    float* out = (float*)d_out;

    prep_w<<<6656, 256>>>(Wq, Wk, Wv);

    const int SMEM_G = 67584 + 20480 + 768 * 4;   // 91136
    cudaFuncSetAttribute(fused_qkv, cudaFuncAttributeMaxDynamicSharedMemorySize, SMEM_G);
    fused_qkv<<<dim3(T_TOK / 128, NJ), 256, SMEM_G>>>(x, bq, bk, bv);

    const int SMEM_ATTN = ND * 4 + 128;   // 24704
    cudaFuncSetAttribute(attn_ln, cudaFuncAttributeMaxDynamicSharedMemorySize, SMEM_ATTN);
    attn_ln<<<T_TOK, 192, SMEM_ATTN>>>(x, gamma, beta, out);
}